// round 15
// baseline (speedup 1.0000x reference)
#include <cuda_runtime.h>
#include <cstdint>

#define TPB 512

// ---------------- smem layout (bytes) ----------------
#define ATT_STRIDE 260                               /* floats per row */
#define ATT_OFF 0
#define ATT_BYTES (128 * ATT_STRIDE * 4)             /* 133120 */
#define ASLOT(s) (ATT_BYTES + (s) * 10240)           /* 128 rows x 20 floats */
#define BSLOT(s) (ATT_BYTES + 20480 + (s) * 20480)   /* 256 rows x 20 floats */
#define VA_OFF  (ATT_BYTES + 61440)
#define BZ_OFF  (VA_OFF + 1024)
#define BH_OFF  (BZ_OFF + 1024)
#define RED_OFF (BH_OFF + 1024)
#define SMEM_TOTAL (RED_OFF + 2048)                  /* 199680 */

__device__ __forceinline__ uint32_t cvt_tf32(float f) {
    uint32_t u;
    asm("cvt.rna.tf32.f32 %0, %1;" : "=r"(u) : "f"(f));
    return u;
}

__device__ __forceinline__ void mma8(float* d, const uint32_t* a, const uint32_t* b) {
    asm volatile(
        "mma.sync.aligned.m16n8k8.row.col.f32.tf32.tf32.f32 "
        "{%0,%1,%2,%3}, {%4,%5,%6,%7}, {%8,%9}, {%0,%1,%2,%3};"
        : "+f"(d[0]), "+f"(d[1]), "+f"(d[2]), "+f"(d[3])
        : "r"(a[0]), "r"(a[1]), "r"(a[2]), "r"(a[3]), "r"(b[0]), "r"(b[1]));
}

__device__ __forceinline__ float fast_tanh(float v) {
    float e = __expf(-2.f * fabsf(v));
    float t = __fdividef(1.f - e, 1.f + e);
    return copysignf(t, v);
}
__device__ __forceinline__ float fast_sig(float v) {
    return __fdividef(1.f, 1.f + __expf(-v));
}

// One K=256 accumulation segment, streamed in 16 chunks of K=16 (double
// buffered). A_ATT=true reads the A operand from the resident attended
// buffer (plain [row][ATT_STRIDE] layout) instead of streaming from gmem.
template <bool A_ATT>
__device__ __forceinline__ void run_seg(
    char* sm, const float* __restrict__ Ag, const float* __restrict__ Bg,
    float acc[2][8][4], int tid, int g, int c, int rbase, int nw)
{
    const int arow = tid >> 2, aseg = tid & 3;

    // prologue: fill chunk 0
    if (!A_ATT) {
        float4 v = *reinterpret_cast<const float4*>(Ag + (size_t)arow * 256 + aseg * 4);
        uint4 u = { cvt_tf32(v.x), cvt_tf32(v.y), cvt_tf32(v.z), cvt_tf32(v.w) };
        *reinterpret_cast<uint4*>(sm + ASLOT(0) + arow * 80 + aseg * 16) = u;
    }
    #pragma unroll
    for (int q = 0; q < 2; q++) {
        int r = arow + q * 128;
        float4 v = *reinterpret_cast<const float4*>(Bg + (size_t)r * 256 + aseg * 4);
        uint4 u = { cvt_tf32(v.x), cvt_tf32(v.y), cvt_tf32(v.z), cvt_tf32(v.w) };
        *reinterpret_cast<uint4*>(sm + BSLOT(0) + r * 80 + aseg * 16) = u;
    }
    __syncthreads();

    float4 sa, sb0, sb1;
    for (int kc = 0; kc < 16; kc++) {
        const int cur = kc & 1;
        if (kc < 15) {  // prefetch next chunk into registers
            const int kb = (kc + 1) * 16;
            if (!A_ATT)
                sa = *reinterpret_cast<const float4*>(Ag + (size_t)arow * 256 + kb + aseg * 4);
            sb0 = *reinterpret_cast<const float4*>(Bg + (size_t)arow * 256 + kb + aseg * 4);
            sb1 = *reinterpret_cast<const float4*>(Bg + (size_t)(arow + 128) * 256 + kb + aseg * 4);
        }

        const uint32_t* Bs = reinterpret_cast<const uint32_t*>(sm + BSLOT(cur));
        const uint32_t* As;
        int astr, kof;
        if (A_ATT) { As = reinterpret_cast<const uint32_t*>(sm + ATT_OFF); astr = ATT_STRIDE; kof = kc * 16; }
        else       { As = reinterpret_cast<const uint32_t*>(sm + ASLOT(cur)); astr = 20; kof = 0; }

        #pragma unroll
        for (int t = 0; t < 2; t++) {
            uint32_t afr[2][4];
            const int k = kof + t * 8 + c;
            #pragma unroll
            for (int i = 0; i < 2; i++) {
                const int r0 = rbase + i * 16;
                afr[i][0] = As[r0 * astr + k];
                afr[i][1] = As[(r0 + 8) * astr + k];
                afr[i][2] = As[r0 * astr + k + 4];
                afr[i][3] = As[(r0 + 8) * astr + k + 4];
            }
            #pragma unroll
            for (int j = 0; j < 8; j++) {
                const int n = nw * 64 + j * 8 + g;
                uint32_t bfr[2] = { Bs[n * 20 + t * 8 + c], Bs[n * 20 + t * 8 + c + 4] };
                mma8(acc[0][j], afr[0], bfr);
                mma8(acc[1][j], afr[1], bfr);
            }
        }

        if (kc < 15) {  // commit prefetched chunk to the other slot
            const int nxt = cur ^ 1;
            if (!A_ATT) {
                uint4 u = { cvt_tf32(sa.x), cvt_tf32(sa.y), cvt_tf32(sa.z), cvt_tf32(sa.w) };
                *reinterpret_cast<uint4*>(sm + ASLOT(nxt) + arow * 80 + aseg * 16) = u;
            }
            uint4 u0 = { cvt_tf32(sb0.x), cvt_tf32(sb0.y), cvt_tf32(sb0.z), cvt_tf32(sb0.w) };
            *reinterpret_cast<uint4*>(sm + BSLOT(nxt) + arow * 80 + aseg * 16) = u0;
            uint4 u1 = { cvt_tf32(sb1.x), cvt_tf32(sb1.y), cvt_tf32(sb1.z), cvt_tf32(sb1.w) };
            *reinterpret_cast<uint4*>(sm + BSLOT(nxt) + (arow + 128) * 80 + aseg * 16) = u1;
        }
        __syncthreads();
    }
}

__global__ void __launch_bounds__(TPB) gru_fused_kernel(
    const float* __restrict__ x, const float* __restrict__ hprev,
    const float* __restrict__ Wz, const float* __restrict__ Uz, const float* __restrict__ bz,
    const float* __restrict__ Wa, const float* __restrict__ Ua, const float* __restrict__ va,
    const float* __restrict__ Wh, const float* __restrict__ Uh, const float* __restrict__ bh,
    float* __restrict__ out)
{
    extern __shared__ char sm[];
    const int tid = threadIdx.x;
    const int lane = tid & 31, w = tid >> 5;
    const int g = lane >> 2, c = lane & 3;
    const int mw = w & 3, nw = w >> 2;
    const int rbase = mw * 32 + g;
    const int base = blockIdx.x * 128;

    if (tid < 256) {
        reinterpret_cast<float*>(sm + VA_OFF)[tid] = va[tid];
        reinterpret_cast<float*>(sm + BZ_OFF)[tid] = bz[tid];
        reinterpret_cast<float*>(sm + BH_OFF)[tid] = bh[tid];
    }

    const float* xb = x + (size_t)base * 256;
    const float* hb = hprev + (size_t)base * 256;

    float acc[2][8][4];

    // =========== Phase 1: a_pre = x@Wa^T + h@Ua^T ===========
    #pragma unroll
    for (int i = 0; i < 2; i++)
        #pragma unroll
        for (int j = 0; j < 8; j++)
            #pragma unroll
            for (int e = 0; e < 4; e++) acc[i][j][e] = 0.f;
    run_seg<false>(sm, xb, Wa, acc, tid, g, c, rbase, nw);
    run_seg<false>(sm, hb, Ua, acc, tid, g, c, rbase, nw);

    // ---- Epilogue 1: s = tanh(a_pre)*va, row softmax, attended = attn*h ----
    {
        const float* vas = reinterpret_cast<const float*>(sm + VA_OFF);
        float* red = reinterpret_cast<float*>(sm + RED_OFF);
        float p[2][2][16];
        float mx[2][2], inv[2][2];

        #pragma unroll
        for (int i = 0; i < 2; i++)
            #pragma unroll
            for (int h = 0; h < 2; h++) {
                float m = -1e30f;
                #pragma unroll
                for (int j = 0; j < 8; j++)
                    #pragma unroll
                    for (int e = 0; e < 2; e++) {
                        const int col = nw * 64 + j * 8 + 2 * c + e;
                        float s = fast_tanh(acc[i][j][h * 2 + e]) * vas[col];
                        p[i][h][j * 2 + e] = s;
                        m = fmaxf(m, s);
                    }
                m = fmaxf(m, __shfl_xor_sync(0xffffffffu, m, 1));
                m = fmaxf(m, __shfl_xor_sync(0xffffffffu, m, 2));
                if (c == 0) red[(rbase + i * 16 + h * 8) * 4 + nw] = m;
            }
        __syncthreads();
        #pragma unroll
        for (int i = 0; i < 2; i++)
            #pragma unroll
            for (int h = 0; h < 2; h++) {
                const int row = rbase + i * 16 + h * 8;
                mx[i][h] = fmaxf(fmaxf(red[row * 4], red[row * 4 + 1]),
                                 fmaxf(red[row * 4 + 2], red[row * 4 + 3]));
            }
        __syncthreads();
        #pragma unroll
        for (int i = 0; i < 2; i++)
            #pragma unroll
            for (int h = 0; h < 2; h++) {
                float s = 0.f;
                #pragma unroll
                for (int k = 0; k < 16; k++) {
                    p[i][h][k] = __expf(p[i][h][k] - mx[i][h]);
                    s += p[i][h][k];
                }
                s += __shfl_xor_sync(0xffffffffu, s, 1);
                s += __shfl_xor_sync(0xffffffffu, s, 2);
                if (c == 0) red[(rbase + i * 16 + h * 8) * 4 + nw] = s;
            }
        __syncthreads();
        #pragma unroll
        for (int i = 0; i < 2; i++)
            #pragma unroll
            for (int h = 0; h < 2; h++) {
                const int row = rbase + i * 16 + h * 8;
                inv[i][h] = __frcp_rn(red[row * 4] + red[row * 4 + 1] +
                                      red[row * 4 + 2] + red[row * 4 + 3]);
            }
        #pragma unroll
        for (int i = 0; i < 2; i++)
            #pragma unroll
            for (int h = 0; h < 2; h++) {
                const int row = rbase + i * 16 + h * 8;
                const float2* hg = reinterpret_cast<const float2*>(hb + (size_t)row * 256);
                #pragma unroll
                for (int j = 0; j < 8; j++) {
                    const int col = nw * 64 + j * 8 + 2 * c;
                    float2 hv = hg[col >> 1];
                    uint2 st;
                    st.x = cvt_tf32(p[i][h][j * 2]     * inv[i][h] * hv.x);
                    st.y = cvt_tf32(p[i][h][j * 2 + 1] * inv[i][h] * hv.y);
                    *reinterpret_cast<uint2*>(sm + ATT_OFF + ((size_t)row * ATT_STRIDE + col) * 4) = st;
                }
            }
        __syncthreads();
    }

    // =========== Phase 2: h~_pre = x@Wh^T + attended@Uh^T ===========
    #pragma unroll
    for (int i = 0; i < 2; i++)
        #pragma unroll
        for (int j = 0; j < 8; j++)
            #pragma unroll
            for (int e = 0; e < 4; e++) acc[i][j][e] = 0.f;
    run_seg<false>(sm, xb, Wh, acc, tid, g, c, rbase, nw);
    run_seg<true >(sm, xb, Uh, acc, tid, g, c, rbase, nw);

    // ---- Epilogue 2: h~ = tanh(h~_pre + bh) -> ATT buffer (plain f32) ----
    {
        const float* bhs = reinterpret_cast<const float*>(sm + BH_OFF);
        __syncthreads();   // all reads of attended done before overwrite
        #pragma unroll
        for (int i = 0; i < 2; i++)
            #pragma unroll
            for (int h = 0; h < 2; h++) {
                const int row = rbase + i * 16 + h * 8;
                #pragma unroll
                for (int j = 0; j < 8; j++) {
                    const int col = nw * 64 + j * 8 + 2 * c;
                    float2 t;
                    t.x = fast_tanh(acc[i][j][h * 2]     + bhs[col]);
                    t.y = fast_tanh(acc[i][j][h * 2 + 1] + bhs[col + 1]);
                    *reinterpret_cast<float2*>(sm + ATT_OFF + ((size_t)row * ATT_STRIDE + col) * 4) = t;
                }
            }
    }

    // =========== Phase 3: z_pre = x@Wz^T + h@Uz^T ===========
    #pragma unroll
    for (int i = 0; i < 2; i++)
        #pragma unroll
        for (int j = 0; j < 8; j++)
            #pragma unroll
            for (int e = 0; e < 4; e++) acc[i][j][e] = 0.f;
    run_seg<false>(sm, xb, Wz, acc, tid, g, c, rbase, nw);
    run_seg<false>(sm, hb, Uz, acc, tid, g, c, rbase, nw);

    // ---- Epilogue 3: z = sigmoid(z_pre + bz); out = (1-z)*h + z*h~ ----
    {
        const float* bzs = reinterpret_cast<const float*>(sm + BZ_OFF);
        #pragma unroll
        for (int i = 0; i < 2; i++)
            #pragma unroll
            for (int h = 0; h < 2; h++) {
                const int row = rbase + i * 16 + h * 8;
                const float2* hg = reinterpret_cast<const float2*>(hb + (size_t)row * 256);
                float2* og = reinterpret_cast<float2*>(out + (size_t)(base + row) * 256);
                #pragma unroll
                for (int j = 0; j < 8; j++) {
                    const int col = nw * 64 + j * 8 + 2 * c;
                    float2 hv = hg[col >> 1];
                    float2 ht = *reinterpret_cast<const float2*>(
                        sm + ATT_OFF + ((size_t)row * ATT_STRIDE + col) * 4);
                    float z0 = fast_sig(acc[i][j][h * 2]     + bzs[col]);
                    float z1 = fast_sig(acc[i][j][h * 2 + 1] + bzs[col + 1]);
                    float2 o;
                    o.x = (1.f - z0) * hv.x + z0 * ht.x;
                    o.y = (1.f - z1) * hv.y + z1 * ht.y;
                    og[col >> 1] = o;
                }
            }
    }
}

extern "C" void kernel_launch(void* const* d_in, const int* in_sizes, int n_in,
                              void* d_out, int out_size) {
    const float* x  = (const float*)d_in[0];
    const float* h  = (const float*)d_in[1];
    const float* Wz = (const float*)d_in[2];
    const float* Uz = (const float*)d_in[3];
    const float* bz = (const float*)d_in[4];
    const float* Wa = (const float*)d_in[5];
    const float* Ua = (const float*)d_in[6];
    const float* va = (const float*)d_in[7];
    const float* Wh = (const float*)d_in[8];
    const float* Uh = (const float*)d_in[9];
    const float* bh = (const float*)d_in[10];
    float* out = (float*)d_out;

    const int B = in_sizes[0] / 256;   // 65536
    static bool attr_set = false;
    if (!attr_set) {
        cudaFuncSetAttribute(gru_fused_kernel,
                             cudaFuncAttributeMaxDynamicSharedMemorySize, SMEM_TOTAL);
        attr_set = true;
    }
    gru_fused_kernel<<<B / 128, TPB, SMEM_TOTAL>>>(
        x, h, Wz, Uz, bz, Wa, Ua, va, Wh, Uh, bh, out);
}

// round 16
// speedup vs baseline: 1.1670x; 1.1670x over previous
#include <cuda_runtime.h>
#include <cstdint>

#define TPB 256

// ---------------- smem layout (bytes) ----------------
// A slots: 64 rows x 36 floats (K=32 + 4 pad)  -> 9216 B each
// B slots: 256 rows x 36 floats                -> 36864 B each
#define AS 36
#define BSTR 36
#define ASLOT(s) ((s) * 9216)
#define BSLOT(s) (18432 + (s) * 36864)
#define RED_OFF 92160
#define SMEM_TOTAL 93184            /* x2 CTAs = 186368 <= 227KB carveout */

// gmem scratch for attended / h_tilde (write->read within the same CTA only)
__device__ float g_att[(size_t)65536 * 256];

__device__ __forceinline__ uint32_t cvt_tf32(float f) {
    uint32_t u;
    asm("cvt.rna.tf32.f32 %0, %1;" : "=r"(u) : "f"(f));
    return u;
}

__device__ __forceinline__ void mma8(float* d, const uint32_t* a, const uint32_t* b) {
    asm volatile(
        "mma.sync.aligned.m16n8k8.row.col.f32.tf32.tf32.f32 "
        "{%0,%1,%2,%3}, {%4,%5,%6,%7}, {%8,%9}, {%0,%1,%2,%3};"
        : "+f"(d[0]), "+f"(d[1]), "+f"(d[2]), "+f"(d[3])
        : "r"(a[0]), "r"(a[1]), "r"(a[2]), "r"(a[3]), "r"(b[0]), "r"(b[1]));
}

__device__ __forceinline__ float fast_tanh(float v) {
    float e = __expf(-2.f * fabsf(v));
    float t = __fdividef(1.f - e, 1.f + e);
    return copysignf(t, v);
}
__device__ __forceinline__ float fast_sig(float v) {
    return __fdividef(1.f, 1.f + __expf(-v));
}

__device__ __forceinline__ void sts_quad(char* sm, int off_bytes, float4 v) {
    uint4 u = { cvt_tf32(v.x), cvt_tf32(v.y), cvt_tf32(v.z), cvt_tf32(v.w) };
    *reinterpret_cast<uint4*>(sm + off_bytes) = u;
}

// One MMA step over k8 index t on the slot pointed to by Asp/Bsp.
__device__ __forceinline__ void mma_step(
    const uint32_t* Asp, const uint32_t* Bsp, float acc[2][8][4],
    int t, int g, int c, int rbase, int nw)
{
    const int k = t * 8 + c;
    uint32_t afr[2][4];
    #pragma unroll
    for (int i = 0; i < 2; i++) {
        const int r0 = rbase + i * 16;
        afr[i][0] = Asp[r0 * AS + k];
        afr[i][1] = Asp[(r0 + 8) * AS + k];
        afr[i][2] = Asp[r0 * AS + k + 4];
        afr[i][3] = Asp[(r0 + 8) * AS + k + 4];
    }
    #pragma unroll
    for (int j = 0; j < 8; j++) {
        const int n = nw * 64 + j * 8 + g;
        uint32_t bf[2] = { Bsp[n * BSTR + k], Bsp[n * BSTR + k + 4] };
        mma8(acc[0][j], afr[0], bf);
        mma8(acc[1][j], afr[1], bf);
    }
}

// One full phase: acc += A0[64x256] @ B0^T + A1[64x256] @ B1^T,
// streamed as 16 chunks of K=32, double-buffered, 1 sync per chunk.
__device__ __forceinline__ void run_phase(
    char* sm, const float* __restrict__ A0, const float* __restrict__ B0,
    const float* __restrict__ A1, const float* __restrict__ B1,
    float acc[2][8][4], int tid, int g, int c, int rbase, int nw)
{
    const int arow = tid >> 2;
    const int aseg = (tid & 3) * 8;

    // prologue: chunk 0 (A0/B0, cols 0..31)
    {
        float4 v0 = *reinterpret_cast<const float4*>(A0 + (size_t)arow * 256 + aseg);
        float4 v1 = *reinterpret_cast<const float4*>(A0 + (size_t)arow * 256 + aseg + 4);
        sts_quad(sm, ASLOT(0) + (arow * AS + aseg) * 4, v0);
        sts_quad(sm, ASLOT(0) + (arow * AS + aseg + 4) * 4, v1);
        #pragma unroll
        for (int q = 0; q < 4; q++) {
            const int r = arow + q * 64;
            float4 w0 = *reinterpret_cast<const float4*>(B0 + (size_t)r * 256 + aseg);
            float4 w1 = *reinterpret_cast<const float4*>(B0 + (size_t)r * 256 + aseg + 4);
            sts_quad(sm, BSLOT(0) + (r * BSTR + aseg) * 4, w0);
            sts_quad(sm, BSLOT(0) + (r * BSTR + aseg + 4) * 4, w1);
        }
    }
    __syncthreads();

    #pragma unroll 2
    for (int kc = 0; kc < 16; kc++) {
        const int cur = kc & 1, nxt = cur ^ 1;
        const bool pf = (kc < 15);
        const float* An = ((kc + 1) < 8) ? A0 : A1;
        const float* Bn = ((kc + 1) < 8) ? B0 : B1;
        const int cb = ((kc + 1) & 7) * 32 + aseg;

        const uint32_t* Asp = reinterpret_cast<const uint32_t*>(sm + ASLOT(cur));
        const uint32_t* Bsp = reinterpret_cast<const uint32_t*>(sm + BSLOT(cur));

        // wave 1: prefetch A + B rows {arow, arow+64}
        float4 a0, a1, w00, w01, w10, w11;
        if (pf) {
            a0  = *reinterpret_cast<const float4*>(An + (size_t)arow * 256 + cb);
            a1  = *reinterpret_cast<const float4*>(An + (size_t)arow * 256 + cb + 4);
            w00 = *reinterpret_cast<const float4*>(Bn + (size_t)arow * 256 + cb);
            w01 = *reinterpret_cast<const float4*>(Bn + (size_t)arow * 256 + cb + 4);
            w10 = *reinterpret_cast<const float4*>(Bn + (size_t)(arow + 64) * 256 + cb);
            w11 = *reinterpret_cast<const float4*>(Bn + (size_t)(arow + 64) * 256 + cb + 4);
        }

        mma_step(Asp, Bsp, acc, 0, g, c, rbase, nw);
        mma_step(Asp, Bsp, acc, 1, g, c, rbase, nw);

        if (pf) {
            sts_quad(sm, ASLOT(nxt) + (arow * AS + aseg) * 4, a0);
            sts_quad(sm, ASLOT(nxt) + (arow * AS + aseg + 4) * 4, a1);
            sts_quad(sm, BSLOT(nxt) + (arow * BSTR + aseg) * 4, w00);
            sts_quad(sm, BSLOT(nxt) + (arow * BSTR + aseg + 4) * 4, w01);
            sts_quad(sm, BSLOT(nxt) + ((arow + 64) * BSTR + aseg) * 4, w10);
            sts_quad(sm, BSLOT(nxt) + ((arow + 64) * BSTR + aseg + 4) * 4, w11);
        }

        // wave 2: prefetch B rows {arow+128, arow+192}
        float4 w20, w21, w30, w31;
        if (pf) {
            w20 = *reinterpret_cast<const float4*>(Bn + (size_t)(arow + 128) * 256 + cb);
            w21 = *reinterpret_cast<const float4*>(Bn + (size_t)(arow + 128) * 256 + cb + 4);
            w30 = *reinterpret_cast<const float4*>(Bn + (size_t)(arow + 192) * 256 + cb);
            w31 = *reinterpret_cast<const float4*>(Bn + (size_t)(arow + 192) * 256 + cb + 4);
        }

        mma_step(Asp, Bsp, acc, 2, g, c, rbase, nw);
        mma_step(Asp, Bsp, acc, 3, g, c, rbase, nw);

        if (pf) {
            sts_quad(sm, BSLOT(nxt) + ((arow + 128) * BSTR + aseg) * 4, w20);
            sts_quad(sm, BSLOT(nxt) + ((arow + 128) * BSTR + aseg + 4) * 4, w21);
            sts_quad(sm, BSLOT(nxt) + ((arow + 192) * BSTR + aseg) * 4, w30);
            sts_quad(sm, BSLOT(nxt) + ((arow + 192) * BSTR + aseg + 4) * 4, w31);
        }
        __syncthreads();
    }
}

#define ZERO_ACC() \
    _Pragma("unroll") for (int i = 0; i < 2; i++) \
    _Pragma("unroll") for (int j = 0; j < 8; j++) \
    _Pragma("unroll") for (int e = 0; e < 4; e++) acc[i][j][e] = 0.f

__global__ void __launch_bounds__(TPB, 2) gru_fused_kernel(
    const float* __restrict__ x, const float* __restrict__ hprev,
    const float* __restrict__ Wz, const float* __restrict__ Uz, const float* __restrict__ bz,
    const float* __restrict__ Wa, const float* __restrict__ Ua, const float* __restrict__ va,
    const float* __restrict__ Wh, const float* __restrict__ Uh, const float* __restrict__ bh,
    float* __restrict__ out)
{
    extern __shared__ char sm[];
    const int tid = threadIdx.x;
    const int lane = tid & 31, w = tid >> 5;
    const int g = lane >> 2, c = lane & 3;
    const int mw = w & 1, nw = w >> 1;            // 2 M-tiles x 4 N-tiles
    const int rbase = mw * 32 + g;
    const int base = blockIdx.x * 64;

    const float* xb = x + (size_t)base * 256;
    const float* hb = hprev + (size_t)base * 256;
    float* attb = g_att + (size_t)base * 256;

    float acc[2][8][4];

    // =========== Phase 1: a_pre = x@Wa^T + h@Ua^T ===========
    ZERO_ACC();
    run_phase(sm, xb, Wa, hb, Ua, acc, tid, g, c, rbase, nw);

    // ---- Epilogue 1: s = tanh(a_pre)*va, row softmax, attended -> gmem ----
    {
        float* red = reinterpret_cast<float*>(sm + RED_OFF);
        float p[2][2][16];
        float mx[2][2], inv[2][2];

        #pragma unroll
        for (int i = 0; i < 2; i++)
            #pragma unroll
            for (int h = 0; h < 2; h++) {
                float m = -1e30f;
                #pragma unroll
                for (int j = 0; j < 8; j++)
                    #pragma unroll
                    for (int e = 0; e < 2; e++) {
                        const int col = nw * 64 + j * 8 + 2 * c + e;
                        float s = fast_tanh(acc[i][j][h * 2 + e]) * __ldg(&va[col]);
                        p[i][h][j * 2 + e] = s;
                        m = fmaxf(m, s);
                    }
                m = fmaxf(m, __shfl_xor_sync(0xffffffffu, m, 1));
                m = fmaxf(m, __shfl_xor_sync(0xffffffffu, m, 2));
                if (c == 0) red[(rbase + i * 16 + h * 8) * 4 + nw] = m;
            }
        __syncthreads();
        #pragma unroll
        for (int i = 0; i < 2; i++)
            #pragma unroll
            for (int h = 0; h < 2; h++) {
                const int row = rbase + i * 16 + h * 8;
                mx[i][h] = fmaxf(fmaxf(red[row * 4], red[row * 4 + 1]),
                                 fmaxf(red[row * 4 + 2], red[row * 4 + 3]));
            }
        __syncthreads();
        #pragma unroll
        for (int i = 0; i < 2; i++)
            #pragma unroll
            for (int h = 0; h < 2; h++) {
                float s = 0.f;
                #pragma unroll
                for (int k = 0; k < 16; k++) {
                    p[i][h][k] = __expf(p[i][h][k] - mx[i][h]);
                    s += p[i][h][k];
                }
                s += __shfl_xor_sync(0xffffffffu, s, 1);
                s += __shfl_xor_sync(0xffffffffu, s, 2);
                if (c == 0) red[(rbase + i * 16 + h * 8) * 4 + nw] = s;
            }
        __syncthreads();
        #pragma unroll
        for (int i = 0; i < 2; i++)
            #pragma unroll
            for (int h = 0; h < 2; h++) {
                const int row = rbase + i * 16 + h * 8;
                inv[i][h] = __frcp_rn(red[row * 4] + red[row * 4 + 1] +
                                      red[row * 4 + 2] + red[row * 4 + 3]);
            }
        #pragma unroll
        for (int i = 0; i < 2; i++)
            #pragma unroll
            for (int h = 0; h < 2; h++) {
                const int row = rbase + i * 16 + h * 8;
                const float2* hg = reinterpret_cast<const float2*>(hb + (size_t)row * 256);
                float2* ag = reinterpret_cast<float2*>(attb + (size_t)row * 256);
                #pragma unroll
                for (int j = 0; j < 8; j++) {
                    const int col = nw * 64 + j * 8 + 2 * c;
                    float2 hv = hg[col >> 1];
                    float2 av;
                    av.x = p[i][h][j * 2]     * inv[i][h] * hv.x;
                    av.y = p[i][h][j * 2 + 1] * inv[i][h] * hv.y;
                    ag[col >> 1] = av;
                }
            }
    }

    // =========== Phase 2: h~_pre = x@Wh^T + attended@Uh^T ===========
    ZERO_ACC();
    run_phase(sm, xb, Wh, attb, Uh, acc, tid, g, c, rbase, nw);

    // ---- Epilogue 2: h~ = tanh(h~_pre + bh) -> gmem (overwrite attended) ----
    #pragma unroll
    for (int i = 0; i < 2; i++)
        #pragma unroll
        for (int h = 0; h < 2; h++) {
            const int row = rbase + i * 16 + h * 8;
            float2* ag = reinterpret_cast<float2*>(attb + (size_t)row * 256);
            #pragma unroll
            for (int j = 0; j < 8; j++) {
                const int col = nw * 64 + j * 8 + 2 * c;
                float2 t;
                t.x = fast_tanh(acc[i][j][h * 2]     + __ldg(&bh[col]));
                t.y = fast_tanh(acc[i][j][h * 2 + 1] + __ldg(&bh[col + 1]));
                ag[col >> 1] = t;
            }
        }

    // =========== Phase 3: z_pre = x@Wz^T + h@Uz^T ===========
    ZERO_ACC();
    run_phase(sm, xb, Wz, hb, Uz, acc, tid, g, c, rbase, nw);

    // ---- Epilogue 3: z = sigmoid(z_pre + bz); out = (1-z)*h + z*h~ ----
    #pragma unroll
    for (int i = 0; i < 2; i++)
        #pragma unroll
        for (int h = 0; h < 2; h++) {
            const int row = rbase + i * 16 + h * 8;
            const float2* hg = reinterpret_cast<const float2*>(hb + (size_t)row * 256);
            const float2* tg = reinterpret_cast<const float2*>(attb + (size_t)row * 256);
            float2* og = reinterpret_cast<float2*>(out + (size_t)(base + row) * 256);
            #pragma unroll
            for (int j = 0; j < 8; j++) {
                const int col = nw * 64 + j * 8 + 2 * c;
                float2 hv = hg[col >> 1];
                float2 ht = tg[col >> 1];
                float z0 = fast_sig(acc[i][j][h * 2]     + __ldg(&bz[col]));
                float z1 = fast_sig(acc[i][j][h * 2 + 1] + __ldg(&bz[col + 1]));
                float2 o;
                o.x = (1.f - z0) * hv.x + z0 * ht.x;
                o.y = (1.f - z1) * hv.y + z1 * ht.y;
                og[col >> 1] = o;
            }
        }
}

extern "C" void kernel_launch(void* const* d_in, const int* in_sizes, int n_in,
                              void* d_out, int out_size) {
    const float* x  = (const float*)d_in[0];
    const float* h  = (const float*)d_in[1];
    const float* Wz = (const float*)d_in[2];
    const float* Uz = (const float*)d_in[3];
    const float* bz = (const float*)d_in[4];
    const float* Wa = (const float*)d_in[5];
    const float* Ua = (const float*)d_in[6];
    const float* va = (const float*)d_in[7];
    const float* Wh = (const float*)d_in[8];
    const float* Uh = (const float*)d_in[9];
    const float* bh = (const float*)d_in[10];
    float* out = (float*)d_out;

    const int B = in_sizes[0] / 256;   // 65536
    cudaFuncSetAttribute(gru_fused_kernel,
                         cudaFuncAttributeMaxDynamicSharedMemorySize, SMEM_TOTAL);
    gru_fused_kernel<<<B / 64, TPB, SMEM_TOTAL>>>(
        x, h, Wz, Uz, bz, Wa, Ua, va, Wh, Uh, bh, out);
}